// round 1
// baseline (speedup 1.0000x reference)
#include <cuda_runtime.h>
#include <math.h>

// Problem constants
#define BSZ   4
#define NLEN  4096
#define DIM_  1024
#define HEADS 16
#define HD    64
#define FEAT  256
#define ROWS  (BSZ * NLEN)   // 16384
#define GSPLIT 8

// ---------------- scratch (__device__ globals; no allocation allowed) ------
__device__ float g_q[(size_t)ROWS * DIM_];                       // elu(q)+1
__device__ float g_k[(size_t)ROWS * DIM_];                       // elu(k)+1
__device__ float g_v[(size_t)ROWS * DIM_];                       // v
__device__ float g_Gpart[(size_t)GSPLIT * BSZ * HEADS * HD * HD];
__device__ float g_P[HD * HD];                                   // RF @ RF^T
__device__ float g_M[(size_t)BSZ * HEADS * HD * HD];             // P @ G
__device__ float g_W2[(size_t)BSZ * DIM_ * DIM_];                // blockdiag(M) @ Wo

__device__ __forceinline__ float act_elu1(float x) {
    // elu(x)+1 : x>0 ? x+1 : exp(x)
    return x > 0.f ? x + 1.f : expf(x);
}

// ---------------- SGEMM: C = A(MxK) @ B(KxN) + bias, optional elu+1 --------
// BM=128, BN=128, BK=8, 256 threads, 8x8 per-thread microtile.
template <int ACT>
__global__ __launch_bounds__(256) void sgemm_bias_act(
    const float* __restrict__ A, const float* __restrict__ Bm,
    const float* __restrict__ bias, float* __restrict__ C,
    int M, int N, int K, long sA, long sB, long sC)
{
    __shared__ float As[8][128];
    __shared__ float Bs[8][128];

    long bz = blockIdx.z;
    A  += bz * sA;
    Bm += bz * sB;
    C  += bz * sC;

    const int tid  = threadIdx.x;
    const int brow = blockIdx.y * 128;
    const int bcol = blockIdx.x * 128;

    const int tr = (tid / 16) * 8;   // row of microtile within block tile
    const int tc = (tid % 16) * 8;   // col

    const int arow = tid >> 1;            // 0..127
    const int acol = (tid & 1) * 4;       // 0 or 4
    const int brw  = tid >> 5;            // 0..7
    const int bcl  = (tid & 31) * 4;      // 0..124

    const float* Aptr = A + (long)(brow + arow) * K + acol;
    const float* Bptr = Bm + (long)brw * N + bcol + bcl;

    float acc[8][8];
#pragma unroll
    for (int i = 0; i < 8; i++)
#pragma unroll
        for (int j = 0; j < 8; j++) acc[i][j] = 0.f;

    for (int k0 = 0; k0 < K; k0 += 8) {
        float4 av = *(const float4*)(Aptr + k0);
        float4 bv = *(const float4*)(Bptr + (long)k0 * N);
        As[acol + 0][arow] = av.x;
        As[acol + 1][arow] = av.y;
        As[acol + 2][arow] = av.z;
        As[acol + 3][arow] = av.w;
        *(float4*)&Bs[brw][bcl] = bv;
        __syncthreads();

#pragma unroll
        for (int kk = 0; kk < 8; kk++) {
            float ar[8], br[8];
#pragma unroll
            for (int i = 0; i < 8; i++) ar[i] = As[kk][tr + i];
#pragma unroll
            for (int j = 0; j < 8; j++) br[j] = Bs[kk][tc + j];
#pragma unroll
            for (int i = 0; i < 8; i++)
#pragma unroll
                for (int j = 0; j < 8; j++)
                    acc[i][j] = fmaf(ar[i], br[j], acc[i][j]);
        }
        __syncthreads();
    }

    // epilogue: bias + optional activation, vectorized stores
#pragma unroll
    for (int i = 0; i < 8; i++) {
        long crow = brow + tr + i;
#pragma unroll
        for (int j = 0; j < 8; j += 4) {
            int col = bcol + tc + j;
            float4 o;
            o.x = acc[i][j + 0] + bias[col + 0];
            o.y = acc[i][j + 1] + bias[col + 1];
            o.z = acc[i][j + 2] + bias[col + 2];
            o.w = acc[i][j + 3] + bias[col + 3];
            if (ACT == 1) {
                o.x = act_elu1(o.x);
                o.y = act_elu1(o.y);
                o.z = act_elu1(o.z);
                o.w = act_elu1(o.w);
            }
            *(float4*)(C + crow * N + col) = o;
        }
    }
}

// ---------------- P = RF @ RF^T (64x64) ------------------------------------
__global__ __launch_bounds__(256) void pmat_kernel(const float* __restrict__ RF,
                                                   float* __restrict__ P)
{
    __shared__ float RFs[64][65];   // one 64-wide F slab at a time
    const int tid = threadIdx.x;
    const int i  = tid / 4;          // output row e
    const int j0 = (tid % 4) * 16;   // output col start
    float acc[16];
#pragma unroll
    for (int j = 0; j < 16; j++) acc[j] = 0.f;

    for (int f0 = 0; f0 < FEAT; f0 += 64) {
        // load RF[:, f0:f0+64]: 64x64 floats, coalesced
        for (int t = tid; t < 64 * 16; t += 256) {
            int r = t / 16, c4 = (t % 16) * 4;
            float4 v = *(const float4*)(RF + (long)r * FEAT + f0 + c4);
            RFs[r][c4 + 0] = v.x;
            RFs[r][c4 + 1] = v.y;
            RFs[r][c4 + 2] = v.z;
            RFs[r][c4 + 3] = v.w;
        }
        __syncthreads();
#pragma unroll 8
        for (int f = 0; f < 64; f++) {
            float a = RFs[i][f];
#pragma unroll
            for (int j = 0; j < 16; j++)
                acc[j] = fmaf(a, RFs[j0 + j][f], acc[j]);
        }
        __syncthreads();
    }
#pragma unroll
    for (int j = 0; j < 16; j++) P[i * HD + j0 + j] = acc[j];
}

// ---------------- G partials: G(b,h) += k1[chunk]^T @ v[chunk] --------------
// grid: (B*H, GSPLIT); 256 threads; 4x4 per-thread microtile of 64x64 output.
__global__ __launch_bounds__(256) void kv_outer_kernel(const float* __restrict__ Kmat,
                                                       const float* __restrict__ Vmat,
                                                       float* __restrict__ Gp)
{
    const int bh = blockIdx.x;
    const int b = bh / HEADS, h = bh % HEADS;
    const int split = blockIdx.y;
    const int n0 = split * (NLEN / GSPLIT);
    const int CH = 32;

    __shared__ float Ks[CH][HD];
    __shared__ float Vs[CH][HD];

    const int tid = threadIdx.x;
    const int ty = tid / 16, tx = tid % 16;
    float acc[4][4];
#pragma unroll
    for (int i = 0; i < 4; i++)
#pragma unroll
        for (int j = 0; j < 4; j++) acc[i][j] = 0.f;

    const long base = ((long)b * NLEN) * DIM_ + h * HD;

    for (int n = n0; n < n0 + NLEN / GSPLIT; n += CH) {
        for (int t = tid; t < CH * 16; t += 256) {   // 512 float4 loads, 2 per thread
            int r = t / 16, c4 = (t % 16) * 4;
            *(float4*)&Ks[r][c4] = *(const float4*)(Kmat + base + (long)(n + r) * DIM_ + c4);
            *(float4*)&Vs[r][c4] = *(const float4*)(Vmat + base + (long)(n + r) * DIM_ + c4);
        }
        __syncthreads();
#pragma unroll
        for (int kk = 0; kk < CH; kk++) {
            float kr[4], vr[4];
#pragma unroll
            for (int i = 0; i < 4; i++) kr[i] = Ks[kk][ty * 4 + i];
#pragma unroll
            for (int j = 0; j < 4; j++) vr[j] = Vs[kk][tx * 4 + j];
#pragma unroll
            for (int i = 0; i < 4; i++)
#pragma unroll
                for (int j = 0; j < 4; j++)
                    acc[i][j] = fmaf(kr[i], vr[j], acc[i][j]);
        }
        __syncthreads();
    }

    float* out = Gp + ((long)split * BSZ * HEADS + bh) * HD * HD;
#pragma unroll
    for (int i = 0; i < 4; i++)
#pragma unroll
        for (int j = 0; j < 4; j++)
            out[(ty * 4 + i) * HD + tx * 4 + j] = acc[i][j];
}

// ---------------- reduce G partials, M = P @ G ------------------------------
__global__ __launch_bounds__(256) void gm_kernel(const float* __restrict__ Gp,
                                                 const float* __restrict__ P,
                                                 float* __restrict__ Mout)
{
    const int bh = blockIdx.x;
    __shared__ float Gs[HD][HD];
    __shared__ float Ps[HD][HD];
    const int tid = threadIdx.x;

    for (int t = tid; t < HD * HD; t += 256) {
        float s = 0.f;
#pragma unroll
        for (int sp = 0; sp < GSPLIT; sp++)
            s += Gp[((long)sp * BSZ * HEADS + bh) * HD * HD + t];
        Gs[t / HD][t % HD] = s;
        Ps[t / HD][t % HD] = P[t];
    }
    __syncthreads();

    const int e = tid / 4;
    const int d0 = (tid % 4) * 16;
    float acc[16];
#pragma unroll
    for (int j = 0; j < 16; j++) acc[j] = 0.f;
#pragma unroll 8
    for (int c = 0; c < HD; c++) {
        float pe = Ps[e][c];
#pragma unroll
        for (int j = 0; j < 16; j++)
            acc[j] = fmaf(pe, Gs[c][d0 + j], acc[j]);
    }
#pragma unroll
    for (int j = 0; j < 16; j++)
        Mout[(long)bh * HD * HD + e * HD + d0 + j] = acc[j];
}

// ---------------- W2(b)[(h,e),c] = sum_d M(b,h)[e,d] * Wo[h*64+d, c] --------
// grid: (B*H, DIM/128); 256 threads.
__global__ __launch_bounds__(256) void w2_kernel(const float* __restrict__ Mmat,
                                                 const float* __restrict__ Wo,
                                                 float* __restrict__ W2)
{
    const int bh = blockIdx.x;
    const int b = bh / HEADS, h = bh % HEADS;
    const int c0 = blockIdx.y * 128;

    __shared__ float Ms[HD][HD];
    const int tid = threadIdx.x;
    for (int t = tid; t < HD * HD; t += 256)
        Ms[t / HD][t % HD] = Mmat[(long)bh * HD * HD + t];
    __syncthreads();

    const int col = c0 + (tid & 127);
    const int e0  = (tid >> 7) * 32;
    float acc[32];
#pragma unroll
    for (int e = 0; e < 32; e++) acc[e] = 0.f;
#pragma unroll 4
    for (int d = 0; d < HD; d++) {
        float w = Wo[(long)(h * HD + d) * DIM_ + col];
#pragma unroll
        for (int e = 0; e < 32; e++)
            acc[e] = fmaf(Ms[e0 + e][d], w, acc[e]);
    }
#pragma unroll
    for (int e = 0; e < 32; e++)
        W2[(long)b * DIM_ * DIM_ + (long)(h * HD + e0 + e) * DIM_ + col] = acc[e];
}

// ---------------- launch ----------------------------------------------------
extern "C" void kernel_launch(void* const* d_in, const int* in_sizes, int n_in,
                              void* d_out, int out_size)
{
    const float* x   = (const float*)d_in[0];
    const float* Wq  = (const float*)d_in[1];
    const float* bq  = (const float*)d_in[2];
    const float* Wk  = (const float*)d_in[3];
    const float* bk  = (const float*)d_in[4];
    const float* Wv  = (const float*)d_in[5];
    const float* bv  = (const float*)d_in[6];
    const float* Wo  = (const float*)d_in[7];
    const float* bo  = (const float*)d_in[8];
    const float* RF  = (const float*)d_in[9];
    float* out = (float*)d_out;

    float *qp, *kp, *vp, *gpp, *pp, *mp, *w2p;
    cudaGetSymbolAddress((void**)&qp,  g_q);
    cudaGetSymbolAddress((void**)&kp,  g_k);
    cudaGetSymbolAddress((void**)&vp,  g_v);
    cudaGetSymbolAddress((void**)&gpp, g_Gpart);
    cudaGetSymbolAddress((void**)&pp,  g_P);
    cudaGetSymbolAddress((void**)&mp,  g_M);
    cudaGetSymbolAddress((void**)&w2p, g_W2);

    // 1) QKV projections (+elu+1 on q,k)
    dim3 g1(DIM_ / 128, ROWS / 128, 1);
    sgemm_bias_act<1><<<g1, 256>>>(x, Wq, bq, qp, ROWS, DIM_, DIM_, 0, 0, 0);
    sgemm_bias_act<1><<<g1, 256>>>(x, Wk, bk, kp, ROWS, DIM_, DIM_, 0, 0, 0);
    sgemm_bias_act<0><<<g1, 256>>>(x, Wv, bv, vp, ROWS, DIM_, DIM_, 0, 0, 0);

    // 2) P = RF @ RF^T
    pmat_kernel<<<1, 256>>>(RF, pp);

    // 3) G partials: k1^T v per (b,h), split over N
    kv_outer_kernel<<<dim3(BSZ * HEADS, GSPLIT), 256>>>(kp, vp, gpp);

    // 4) reduce + M = P @ G
    gm_kernel<<<BSZ * HEADS, 256>>>(gpp, pp, mp);

    // 5) W2(b) = blockdiag(M) @ Wo
    w2_kernel<<<dim3(BSZ * HEADS, DIM_ / 128), 256>>>(mp, Wo, w2p);

    // 6) final: out(b) = q1(b) @ W2(b) + bo  (batched)
    dim3 g2(DIM_ / 128, NLEN / 128, BSZ);
    sgemm_bias_act<0><<<g2, 256>>>(qp, w2p, bo, out,
                                   NLEN, DIM_, DIM_,
                                   (long)NLEN * DIM_, (long)DIM_ * DIM_, (long)NLEN * DIM_);
}